// round 12
// baseline (speedup 1.0000x reference)
#include <cuda_runtime.h>
#include <cuda_bf16.h>

// B=16,U=64,W=32,E=300,H=512,Hh=512,C=7,D=1024,N=1024. KPAD=320+512=832.

__device__ float g_c[2][1024][512];
__device__ float g_feat[1024][1024];
__device__ float g_bias[2][2048];
__device__ float g_GX[2][32][1024][2048];     // hoisted x-projection (fp32)
__device__ __nv_bfloat16 g_Xhi[32][1024][320];
__device__ __nv_bfloat16 g_Xlo[32][1024][320];
__device__ __nv_bfloat16 g_Whi[2][2048][832];
__device__ __nv_bfloat16 g_Wlo[2][2048][832];
__device__ __nv_bfloat16 g_Hhi[2][1024][512];
__device__ __nv_bfloat16 g_Hlo[2][1024][512];
__device__ float g_Agg[64][16][3072];
__device__ float g_Apg[64][16][3072];
__device__ float g_q[64][16][1024];
__device__ float g_hist[65][16][1024];
__device__ float g_p0[16][1024];
__device__ float g_p1[16][1024];
__device__ float g_e[16][512];
__device__ float g_ctx[16][1024];
__device__ float g_es[64][16][512];
__device__ float g_P1a[4][16][3072];
__device__ float g_P1b[4][16][3072];
__device__ float g_P2a[4][16][3072];
__device__ float g_P2b[4][16][3072];
__device__ float g_P3a[4][16][1536];
__device__ float g_P3b[4][16][1536];
__device__ int g_bar_cnt;

__device__ __forceinline__ unsigned long long pk2(float v) {
    unsigned long long r; asm("mov.b64 %0, {%1, %1};" : "=l"(r) : "f"(v)); return r;
}
__device__ __forceinline__ unsigned long long fma2(unsigned long long a, unsigned long long b, unsigned long long c) {
    unsigned long long d; asm("fma.rn.f32x2 %0, %1, %2, %3;" : "=l"(d) : "l"(a), "l"(b), "l"(c)); return d;
}
__device__ __forceinline__ float2 upk2(unsigned long long v) {
    float2 f; asm("mov.b64 {%0, %1}, %2;" : "=f"(f.x), "=f"(f.y) : "l"(v)); return f;
}
__device__ __forceinline__ float sigf(float x) { return 1.0f / (1.0f + __expf(-x)); }
__device__ __forceinline__ float tanhfast(float x) { return 2.0f / (1.0f + __expf(-2.0f * x)) - 1.0f; }
__device__ __forceinline__ unsigned sm_u32(const void* p) { return (unsigned)__cvta_generic_to_shared(p); }
__device__ __forceinline__ void ldsm4(unsigned& r0, unsigned& r1, unsigned& r2, unsigned& r3, unsigned a) {
    asm volatile("ldmatrix.sync.aligned.m8n8.x4.shared.b16 {%0,%1,%2,%3},[%4];"
                 : "=r"(r0), "=r"(r1), "=r"(r2), "=r"(r3) : "r"(a));
}
__device__ __forceinline__ void mma_bf16(float c[4], unsigned a0, unsigned a1, unsigned a2, unsigned a3,
                                         unsigned b0, unsigned b1) {
    asm volatile("mma.sync.aligned.m16n8k16.row.col.f32.bf16.bf16.f32 "
                 "{%0,%1,%2,%3},{%4,%5,%6,%7},{%8,%9},{%0,%1,%2,%3};"
                 : "+f"(c[0]), "+f"(c[1]), "+f"(c[2]), "+f"(c[3])
                 : "r"(a0), "r"(a1), "r"(a2), "r"(a3), "r"(b0), "r"(b1));
}

__global__ void zero_kernel() {
    int i = blockIdx.x * 256 + threadIdx.x;
    if (i == 0) g_bar_cnt = 0;
    if (i < 2 * 1024 * 512) {
        (&g_c[0][0][0])[i] = 0.0f;
        (&g_Hhi[0][0][0])[i] = __float2bfloat16(0.0f);
        (&g_Hlo[0][0][0])[i] = __float2bfloat16(0.0f);
    }
    if (i < 65 * 16 * 1024) (&g_hist[0][0][0])[i] = 0.0f;
    if (i < 16 * 1024) { (&g_p0[0][0])[i] = 0.0f; (&g_p1[0][0])[i] = 0.0f; }
    if (i < 16 * 512) (&g_e[0][0])[i] = 0.0f;
}

__global__ void convert_kernel(const float* __restrict__ x,
                               const float* __restrict__ Wfi, const float* __restrict__ Wfh,
                               const float* __restrict__ Wbi, const float* __restrict__ Wbh,
                               const float* __restrict__ bif, const float* __restrict__ bhf,
                               const float* __restrict__ bib, const float* __restrict__ bhb) {
    int i = blockIdx.x * 256 + threadIdx.x;
    if (i < 32 * 1024 * 320) {
        int e = i % 320, r = i / 320;
        int n = r % 1024, t = r / 1024;
        float v = (e < 300) ? x[n * 9600 + t * 300 + e] : 0.0f;
        __nv_bfloat16 h = __float2bfloat16(v);
        (&g_Xhi[0][0][0])[i] = h;
        (&g_Xlo[0][0][0])[i] = __float2bfloat16(v - __bfloat162float(h));
    }
    if (i < 2 * 2048 * 832) {
        int k = i % 832, r = i / 832;
        int jp = r % 2048, d = r / 2048;
        int row = (jp & 3) * 512 + (jp >> 2);
        const float* Wih = d ? Wbi : Wfi;
        const float* Whh = d ? Wbh : Wfh;
        float v = (k < 300) ? Wih[row * 300 + k] : (k < 320 ? 0.0f : Whh[row * 512 + (k - 320)]);
        __nv_bfloat16 h = __float2bfloat16(v);
        (&g_Whi[0][0][0])[i] = h;
        (&g_Wlo[0][0][0])[i] = __float2bfloat16(v - __bfloat162float(h));
    }
    if (i < 2 * 2048) {
        int d = i >> 11, jp = i & 2047;
        int row = (jp & 3) * 512 + (jp >> 2);
        g_bias[d][jp] = (d ? bib[row] + bhb[row] : bif[row] + bhf[row]);
    }
}

// Hoisted x-projection: gx[dir][t][n][jp] = x_t @ Wih^T (hi/lo 3-pass).
// grid (16, 256, 2): n-tile 128, blockIdx.y -> {t, n0}; 60 k-tiles.
__global__ __launch_bounds__(256) void gx_tc() {
    extern __shared__ char smraw[];
    __nv_bfloat16* As = (__nv_bfloat16*)smraw;
    __nv_bfloat16* Bs = (__nv_bfloat16*)(smraw + 12288);
    float* sg = (float*)smraw;

    const int dir = blockIdx.z, n0 = blockIdx.x * 128;
    const int t = blockIdx.y >> 3, m0 = (blockIdx.y & 7) * 128;
    const int tid = threadIdx.x, lane = tid & 31, wid = tid >> 5;
    const int wm = wid >> 2, wn = wid & 3;
    const int r = tid >> 1, hf = (tid & 1) * 8;

    const __nv_bfloat16* xhi = &g_Xhi[t][m0 + r][hf];
    const __nv_bfloat16* xlo = &g_Xlo[t][m0 + r][hf];
    const __nv_bfloat16* whi = &g_Whi[dir][n0 + r][hf];
    const __nv_bfloat16* wlo = &g_Wlo[dir][n0 + r][hf];

    float acc[4][4][4];
#pragma unroll
    for (int mi = 0; mi < 4; mi++)
#pragma unroll
        for (int ni = 0; ni < 4; ni++)
#pragma unroll
            for (int q = 0; q < 4; q++) acc[mi][ni][q] = 0.0f;

    uint4 ra, rb;
    auto fetch = [&](int kkn) {
        int pass = (kkn >= 20) + (kkn >= 40);
        int k = (kkn - pass * 20) * 16;
        ra = *(const uint4*)((pass == 1 ? xlo : xhi) + k);
        rb = *(const uint4*)((pass == 2 ? wlo : whi) + k);
    };

    fetch(0);
    *(uint4*)&As[(0 * 128 + r) * 24 + hf] = ra;
    *(uint4*)&Bs[(0 * 128 + r) * 24 + hf] = rb;
    __syncthreads();

    for (int kk = 0; kk < 60; kk++) {
        int cur = kk & 1;
        if (kk < 59) fetch(kk + 1);
        unsigned a[4][4], bfr[2][4];
#pragma unroll
        for (int mi = 0; mi < 4; mi++) {
            unsigned ad = sm_u32(&As[(cur * 128 + wm * 64 + mi * 16 + (lane & 15)) * 24 + (lane >> 4) * 8]);
            ldsm4(a[mi][0], a[mi][1], a[mi][2], a[mi][3], ad);
        }
#pragma unroll
        for (int nb = 0; nb < 2; nb++) {
            unsigned ad = sm_u32(&Bs[(cur * 128 + wn * 32 + nb * 16 + (lane & 15)) * 24 + (lane >> 4) * 8]);
            ldsm4(bfr[nb][0], bfr[nb][1], bfr[nb][2], bfr[nb][3], ad);
        }
#pragma unroll
        for (int mi = 0; mi < 4; mi++)
#pragma unroll
            for (int ni = 0; ni < 4; ni++)
                mma_bf16(acc[mi][ni], a[mi][0], a[mi][1], a[mi][2], a[mi][3],
                         bfr[ni >> 1][ni & 1], bfr[ni >> 1][(ni & 1) + 2]);
        if (kk < 59) {
            *(uint4*)&As[((cur ^ 1) * 128 + r) * 24 + hf] = ra;
            *(uint4*)&Bs[((cur ^ 1) * 128 + r) * 24 + hf] = rb;
        }
        __syncthreads();
    }

#pragma unroll
    for (int mi = 0; mi < 4; mi++)
#pragma unroll
        for (int ni = 0; ni < 4; ni++) {
            int mm = wm * 64 + mi * 16 + (lane >> 2);
            int jj = wn * 32 + ni * 8 + (lane & 3) * 2;
            sg[mm * 132 + jj]           = acc[mi][ni][0];
            sg[mm * 132 + jj + 1]       = acc[mi][ni][1];
            sg[(mm + 8) * 132 + jj]     = acc[mi][ni][2];
            sg[(mm + 8) * 132 + jj + 1] = acc[mi][ni][3];
        }
    __syncthreads();

#pragma unroll
    for (int l = 0; l < 16; l++) {
        int idx = tid + 256 * l;
        int m = idx >> 5, kk = idx & 31;
        *(float4*)&g_GX[dir][t][m0 + m][n0 + 4 * kk] = *(float4*)&sg[m * 132 + 4 * kk];
    }
}

// Fused tensor-core LSTM step: h-recurrence only (96 k-tiles), gx added in epilogue.
__global__ __launch_bounds__(256) void lstm_tc(int t, int last) {
    extern __shared__ char smraw[];
    __nv_bfloat16* As = (__nv_bfloat16*)smraw;
    __nv_bfloat16* Bs = (__nv_bfloat16*)(smraw + 12288);
    float* sg = (float*)smraw;

    const int dir = blockIdx.z, m0 = blockIdx.y * 128, n0 = blockIdx.x * 128;
    const int tt = dir ? 31 - t : t;
    const int tid = threadIdx.x, lane = tid & 31, wid = tid >> 5;
    const int wm = wid >> 2, wn = wid & 3;
    const int r = tid >> 1, hf = (tid & 1) * 8;

    const __nv_bfloat16* hhi = &g_Hhi[dir][m0 + r][hf];
    const __nv_bfloat16* hlo = &g_Hlo[dir][m0 + r][hf];
    const __nv_bfloat16* whi = &g_Whi[dir][n0 + r][320 + hf];
    const __nv_bfloat16* wlo = &g_Wlo[dir][n0 + r][320 + hf];

    float acc[4][4][4];
#pragma unroll
    for (int mi = 0; mi < 4; mi++)
#pragma unroll
        for (int ni = 0; ni < 4; ni++)
#pragma unroll
            for (int q = 0; q < 4; q++) acc[mi][ni][q] = 0.0f;

    uint4 ra, rb;
    auto fetch = [&](int kkn) {
        int pass = (kkn >= 32) + (kkn >= 64);
        int k = (kkn - pass * 32) * 16;
        ra = *(const uint4*)((pass == 1 ? hlo : hhi) + k);
        rb = *(const uint4*)((pass == 2 ? wlo : whi) + k);
    };

    fetch(0);
    *(uint4*)&As[(0 * 128 + r) * 24 + hf] = ra;
    *(uint4*)&Bs[(0 * 128 + r) * 24 + hf] = rb;
    __syncthreads();

    for (int kk = 0; kk < 96; kk++) {
        int cur = kk & 1;
        if (kk < 95) fetch(kk + 1);
        unsigned a[4][4], bfr[2][4];
#pragma unroll
        for (int mi = 0; mi < 4; mi++) {
            unsigned ad = sm_u32(&As[(cur * 128 + wm * 64 + mi * 16 + (lane & 15)) * 24 + (lane >> 4) * 8]);
            ldsm4(a[mi][0], a[mi][1], a[mi][2], a[mi][3], ad);
        }
#pragma unroll
        for (int nb = 0; nb < 2; nb++) {
            unsigned ad = sm_u32(&Bs[(cur * 128 + wn * 32 + nb * 16 + (lane & 15)) * 24 + (lane >> 4) * 8]);
            ldsm4(bfr[nb][0], bfr[nb][1], bfr[nb][2], bfr[nb][3], ad);
        }
#pragma unroll
        for (int mi = 0; mi < 4; mi++)
#pragma unroll
            for (int ni = 0; ni < 4; ni++)
                mma_bf16(acc[mi][ni], a[mi][0], a[mi][1], a[mi][2], a[mi][3],
                         bfr[ni >> 1][ni & 1], bfr[ni >> 1][(ni & 1) + 2]);
        if (kk < 95) {
            *(uint4*)&As[((cur ^ 1) * 128 + r) * 24 + hf] = ra;
            *(uint4*)&Bs[((cur ^ 1) * 128 + r) * 24 + hf] = rb;
        }
        __syncthreads();
    }

#pragma unroll
    for (int mi = 0; mi < 4; mi++)
#pragma unroll
        for (int ni = 0; ni < 4; ni++) {
            int mm = wm * 64 + mi * 16 + (lane >> 2);
            int jj = wn * 32 + ni * 8 + (lane & 3) * 2;
            sg[mm * 132 + jj]           = acc[mi][ni][0];
            sg[mm * 132 + jj + 1]       = acc[mi][ni][1];
            sg[(mm + 8) * 132 + jj]     = acc[mi][ni][2];
            sg[(mm + 8) * 132 + jj + 1] = acc[mi][ni][3];
        }
    __syncthreads();

#pragma unroll
    for (int l = 0; l < 16; l++) {
        int idx = tid + 256 * l;
        int m = idx >> 5, kk = idx & 31;
        int kglob = (n0 >> 2) + kk, mg = m0 + m;
        float4 gq = *(float4*)&sg[m * 132 + 4 * kk];
        float4 bq = *(const float4*)&g_bias[dir][n0 + 4 * kk];
        float4 xq = *(const float4*)&g_GX[dir][tt][mg][n0 + 4 * kk];
        float gi = gq.x + bq.x + xq.x, gf = gq.y + bq.y + xq.y;
        float gg = gq.z + bq.z + xq.z, go = gq.w + bq.w + xq.w;
        float c = g_c[dir][mg][kglob];
        c = sigf(gf) * c + sigf(gi) * tanhfast(gg);
        float h = sigf(go) * tanhfast(c);
        g_c[dir][mg][kglob] = c;
        __nv_bfloat16 hh = __float2bfloat16(h);
        g_Hhi[dir][mg][kglob] = hh;
        g_Hlo[dir][mg][kglob] = __float2bfloat16(h - __bfloat162float(hh));
        if (last) g_feat[mg][dir * 512 + kglob] = h;
    }
}

__global__ __launch_bounds__(256) void pre_gemm(
    const float* __restrict__ W, const float* __restrict__ bias,
    float* __restrict__ out, int N, int sk, int sj)
{
    __shared__ __align__(16) float As2[16][66];
    __shared__ __align__(16) float Bs2[16][130];
    const int tid = threadIdx.x;
    const int tx = tid & 15, ty = tid >> 4;
    const int m0 = blockIdx.y * 64, j0 = blockIdx.x * 128;
    unsigned long long acc[4][4];
#pragma unroll
    for (int i = 0; i < 4; i++)
#pragma unroll
        for (int c = 0; c < 4; c++) acc[i][c] = 0ULL;
    for (int k0 = 0; k0 < 1024; k0 += 16) {
#pragma unroll
        for (int l = 0; l < 4; l++) {
            int idx = tid + 256 * l;
            int k = idx & 15, rr = m0 + (idx >> 4);
            As2[k][idx >> 4] = g_feat[(rr & 15) * 64 + (rr >> 4)][k0 + k];
        }
#pragma unroll
        for (int l = 0; l < 8; l++) {
            int idx = tid + 256 * l;
            Bs2[idx & 15][idx >> 4] = W[(k0 + (idx & 15)) * sk + (j0 + (idx >> 4)) * sj];
        }
        __syncthreads();
#pragma unroll
        for (int k = 0; k < 16; k++) {
            unsigned long long bv[4];
#pragma unroll
            for (int c = 0; c < 4; c++)
                bv[c] = *reinterpret_cast<const unsigned long long*>(&Bs2[k][2 * tx + 32 * c]);
#pragma unroll
            for (int i = 0; i < 4; i++) {
                unsigned long long av = pk2(As2[k][ty + 16 * i]);
#pragma unroll
                for (int c = 0; c < 4; c++) acc[i][c] = fma2(av, bv[c], acc[i][c]);
            }
        }
        __syncthreads();
    }
#pragma unroll
    for (int i = 0; i < 4; i++) {
        int r = m0 + ty + 16 * i;
#pragma unroll
        for (int c = 0; c < 4; c++) {
            int j = j0 + 2 * tx + 32 * c;
            float2 v = upk2(acc[i][c]);
            out[r * N + j]     = v.x + (bias ? bias[j] : 0.0f);
            out[r * N + j + 1] = v.y + (bias ? bias[j + 1] : 0.0f);
        }
    }
}

// ---------------- persistent phase-2 (identical to passing R10) ------------
__device__ void dev_gemm16(int bx, int ks,
    const float* __restrict__ A1, const float* __restrict__ W1, int K1,
    const float* __restrict__ A2, const float* __restrict__ W2, int K2,
    float* __restrict__ part1, float* __restrict__ part2, int N, float* sm)
{
    float (*As2)[16][18] = (float(*)[16][18])sm;
    float (*Bs2)[16][66] = (float(*)[16][66])(sm + 576);
    const int tid = threadIdx.x;
    const int col = tid & 63, rq = tid >> 6;
    const int j0 = bx * 64;
    const int ka = tid & 15, ra_ = tid >> 4;
    const int it1 = K1 >> 6, itT = it1 + (K2 >> 6);

    float acc1[4] = {0.f, 0.f, 0.f, 0.f};
    float acc2[4] = {0.f, 0.f, 0.f, 0.f};
    float ar, br[4];

    auto fetch = [&](int it) {
        const float* A; const float* W; int K, kb;
        if (it < it1) { A = A1; W = W1; K = K1; kb = ks * (K1 >> 2) + it * 16; }
        else          { A = A2; W = W2; K = K2; kb = ks * (K2 >> 2) + (it - it1) * 16; }
        ar = A[ra_ * K + kb + ka];
#pragma unroll
        for (int l = 0; l < 4; l++) {
            int idx = tid + 256 * l;
            br[l] = W[(j0 + (idx >> 4)) * K + kb + (idx & 15)];
        }
    };

    __syncthreads();
    fetch(0);
    As2[0][ka][ra_] = ar;
#pragma unroll
    for (int l = 0; l < 4; l++) { int idx = tid + 256 * l; Bs2[0][idx & 15][idx >> 4] = br[l]; }
    __syncthreads();

    for (int it = 0; it < itT; it++) {
        int cur = it & 1;
        if (it + 1 < itT) fetch(it + 1);
        float* accp = (it < it1) ? acc1 : acc2;
#pragma unroll
        for (int k = 0; k < 16; k++) {
            float b = Bs2[cur][k][col];
#pragma unroll
            for (int i = 0; i < 4; i++) accp[i] += As2[cur][k][rq * 4 + i] * b;
        }
        if (it + 1 < itT) {
            As2[cur ^ 1][ka][ra_] = ar;
#pragma unroll
            for (int l = 0; l < 4; l++) { int idx = tid + 256 * l; Bs2[cur ^ 1][idx & 15][idx >> 4] = br[l]; }
        }
        __syncthreads();
    }

#pragma unroll
    for (int i = 0; i < 4; i++) {
        int rr = rq * 4 + i;
        part1[(ks * 16 + rr) * N + j0 + col] = acc1[i];
        part2[(ks * 16 + rr) * N + j0 + col] = acc2[i];
    }
}

__device__ void dev_combine(int vb,
    const float* __restrict__ pre, const float* __restrict__ bih, const float* __restrict__ bhh,
    const float* __restrict__ part1, const float* __restrict__ part2,
    const float* __restrict__ h, float* __restrict__ outp, float* __restrict__ out2, int Dh)
{
    int idx = vb * 256 + threadIdx.x;
    if (idx >= 16 * Dh) return;
    int b = idx / Dh, j = idx - b * Dh;
    int G = 3 * Dh;
    float gir = 0.f, giz = 0.f, gin = 0.f, ghr = 0.f, ghz = 0.f, ghn = 0.f;
#pragma unroll
    for (int ks = 0; ks < 4; ks++) {
        const float* p1 = part1 + (ks * 16 + b) * G;
        const float* p2 = part2 + (ks * 16 + b) * G;
        gir += p1[j]; giz += p1[Dh + j]; gin += p1[2 * Dh + j];
        ghr += p2[j]; ghz += p2[Dh + j]; ghn += p2[2 * Dh + j];
    }
    if (pre) {
        const float* pp = pre + b * G;
        gir += pp[j]; giz += pp[Dh + j]; gin += pp[2 * Dh + j];
    } else {
        gir += bih[j]; giz += bih[Dh + j]; gin += bih[2 * Dh + j];
    }
    ghr += bhh[j]; ghz += bhh[Dh + j]; ghn += bhh[2 * Dh + j];
    float rg = sigf(gir + ghr);
    float z = sigf(giz + ghz);
    float n = tanhfast(gin + rg * ghn);
    float o = (1.0f - z) * n + z * h[idx];
    outp[idx] = o;
    if (out2) out2[idx] = o;
}

__device__ void dev_attn(int i, int b, float* sm) {
    float* q_s = sm;
    float* sc = sm + 1024;
    const int tid = threadIdx.x;
    __syncthreads();
#pragma unroll
    for (int l = 0; l < 4; l++) q_s[tid + 256 * l] = g_q[i][b][tid + 256 * l];
    __syncthreads();
    const int wid = tid >> 5, lane = tid & 31;
    for (int t = wid; t <= i; t += 8) {
        float s = 0.0f;
        for (int d = lane; d < 1024; d += 32) s += q_s[d] * g_hist[t][b][d];
#pragma unroll
        for (int o = 16; o; o >>= 1) s += __shfl_xor_sync(0xffffffffu, s, o);
        if (lane == 0) sc[t] = s;
    }
    __syncthreads();
    if (tid < 32) {
        float m = -1e30f;
        for (int t = lane; t <= i; t += 32) m = fmaxf(m, sc[t]);
#pragma unroll
        for (int o = 16; o; o >>= 1) m = fmaxf(m, __shfl_xor_sync(0xffffffffu, m, o));
        float s = 0.0f;
        for (int t = lane; t <= i; t += 32) { float e = __expf(sc[t] - m); sc[t] = e; s += e; }
#pragma unroll
        for (int o = 16; o; o >>= 1) s += __shfl_xor_sync(0xffffffffu, s, o);
        float inv = 1.0f / s;
        for (int t = lane; t <= i; t += 32) sc[t] *= inv;
    }
    __syncthreads();
#pragma unroll
    for (int l = 0; l < 4; l++) {
        int d = tid + 256 * l;
        float a = 0.0f;
        for (int t = 0; t <= i; t++) a += sc[t] * g_hist[t][b][d];
        g_ctx[b][d] = a;
    }
    __syncthreads();
}

#define NBLK 152
__device__ __forceinline__ void gbar(int& target) {
    target += NBLK;
    __syncthreads();
    __threadfence();
    if (threadIdx.x == 0) {
        atomicAdd(&g_bar_cnt, 1);
        while (*(volatile int*)&g_bar_cnt < target) __nanosleep(32);
        __threadfence();
    }
    __syncthreads();
}

__global__ __launch_bounds__(256) void phase2_persist(
    const float* __restrict__ gg_Wih, const float* __restrict__ gg_Whh, const float* __restrict__ gg_bhh,
    const float* __restrict__ pg_Wih, const float* __restrict__ pg_Whh, const float* __restrict__ pg_bhh,
    const float* __restrict__ eg_Wih, const float* __restrict__ eg_Whh,
    const float* __restrict__ eg_bih, const float* __restrict__ eg_bhh)
{
    __shared__ __align__(16) float sm[2688];
    int target = 0;
    const int bk = blockIdx.x;
    float* P1a = &g_P1a[0][0][0];
    float* P1b = &g_P1b[0][0][0];
    float* P2a = &g_P2a[0][0][0];
    float* P2b = &g_P2b[0][0][0];
    float* P3a = &g_P3a[0][0][0];
    float* P3b = &g_P3b[0][0][0];

    for (int i = 0; i <= 64; i++) {
        float* p_cur  = (i & 1) ? &g_p1[0][0] : &g_p0[0][0];
        float* p_prev = (i & 1) ? &g_p0[0][0] : &g_p1[0][0];

        for (int vb = bk; vb < 304; vb += NBLK) {
            if (vb < 192) {
                if (i < 64)
                    dev_gemm16(vb % 48, vb / 48, p_cur, gg_Wih, 1024,
                               &g_hist[i][0][0], gg_Whh, 1024, P1a, P1b, 3072, sm);
            } else if (vb < 208) {
                if (i < 64) dev_attn(i, vb - 192, sm);
            } else {
                if (i >= 1)
                    dev_gemm16((vb - 208) % 24, (vb - 208) / 24, p_prev, eg_Wih, 1024,
                               &g_e[0][0], eg_Whh, 512, P3a, P3b, 1536, sm);
            }
        }
        gbar(target);

        for (int vb = bk; vb < 288; vb += NBLK) {
            if (vb < 64) {
                if (i < 64)
                    dev_combine(vb, &g_Agg[i][0][0], nullptr, gg_bhh, P1a, P1b,
                                &g_hist[i][0][0], &g_hist[i + 1][0][0], nullptr, 1024);
            } else if (vb < 96) {
                if (i >= 1)
                    dev_combine(vb - 64, nullptr, eg_bih, eg_bhh, P3a, P3b,
                                &g_e[0][0], &g_e[0][0], &g_es[i - 1][0][0], 512);
            } else {
                if (i < 64)
                    dev_gemm16((vb - 96) % 48, (vb - 96) / 48, &g_ctx[0][0], pg_Wih, 1024,
                               p_cur, pg_Whh, 1024, P2a, P2b, 3072, sm);
            }
        }
        gbar(target);

        if (i < 64) {
            for (int vb = bk; vb < 64; vb += NBLK)
                dev_combine(vb, &g_Apg[i][0][0], nullptr, pg_bhh, P2a, P2b,
                            p_cur, p_cur, nullptr, 1024);
        }
        gbar(target);
    }
}

__global__ void cls_kernel(const float* __restrict__ cls_W, const float* __restrict__ cls_b,
                           float* __restrict__ out) {
    int u = blockIdx.x, tid = threadIdx.x;
    if (tid >= 112) return;
    int b = tid / 7, c = tid - b * 7;
    float s = cls_b[c];
    const float* w = cls_W + c * 512;
    const float* e = &g_es[u][b][0];
    for (int k = 0; k < 512; k++) s += e[k] * w[k];
    out[(b * 64 + u) * 7 + c] = s;
}

extern "C" void kernel_launch(void* const* d_in, const int* in_sizes, int n_in,
                              void* d_out, int out_size) {
    const float* x      = (const float*)d_in[0];
    const float* lWih_f = (const float*)d_in[1];
    const float* lWhh_f = (const float*)d_in[2];
    const float* lbih_f = (const float*)d_in[3];
    const float* lbhh_f = (const float*)d_in[4];
    const float* lWih_b = (const float*)d_in[5];
    const float* lWhh_b = (const float*)d_in[6];
    const float* lbih_b = (const float*)d_in[7];
    const float* lbhh_b = (const float*)d_in[8];
    const float* gg_Wih = (const float*)d_in[9];
    const float* gg_Whh = (const float*)d_in[10];
    const float* gg_bih = (const float*)d_in[11];
    const float* gg_bhh = (const float*)d_in[12];
    const float* Wg     = (const float*)d_in[13];
    const float* pg_Wih = (const float*)d_in[14];
    const float* pg_Whh = (const float*)d_in[15];
    const float* pg_bih = (const float*)d_in[16];
    const float* pg_bhh = (const float*)d_in[17];
    const float* eg_Wih = (const float*)d_in[18];
    const float* eg_Whh = (const float*)d_in[19];
    const float* eg_bih = (const float*)d_in[20];
    const float* eg_bhh = (const float*)d_in[21];
    const float* cls_W  = (const float*)d_in[22];
    const float* cls_b  = (const float*)d_in[23];
    float* out = (float*)d_out;

    float *pAgg, *pApg, *pQ;
    cudaGetSymbolAddress((void**)&pAgg, g_Agg);
    cudaGetSymbolAddress((void**)&pApg, g_Apg);
    cudaGetSymbolAddress((void**)&pQ, g_q);

    static int smem_set = 0;
    if (!smem_set) {
        cudaFuncSetAttribute(lstm_tc, cudaFuncAttributeMaxDynamicSharedMemorySize, 128 * 132 * 4);
        cudaFuncSetAttribute(gx_tc, cudaFuncAttributeMaxDynamicSharedMemorySize, 128 * 132 * 4);
        smem_set = 1;
    }

    zero_kernel<<<4160, 256>>>();
    convert_kernel<<<40960, 256>>>(x, lWih_f, lWhh_f, lWih_b, lWhh_b,
                                   lbih_f, lbhh_f, lbih_b, lbhh_b);

    gx_tc<<<dim3(16, 256, 2), 256, 128 * 132 * 4>>>();

    for (int t = 0; t < 32; t++)
        lstm_tc<<<dim3(16, 8, 2), 256, 128 * 132 * 4>>>(t, t == 31);

    pre_gemm<<<dim3(24, 16), 256>>>(gg_Wih, gg_bih, pAgg, 3072, 1, 1024);
    pre_gemm<<<dim3(24, 16), 256>>>(pg_Wih, pg_bih, pApg, 3072, 1, 1024);
    pre_gemm<<<dim3(8, 16), 256>>>(Wg, nullptr, pQ, 1024, 1024, 1);

    phase2_persist<<<NBLK, 256>>>(gg_Wih, gg_Whh, gg_bhh,
                                  pg_Wih, pg_Whh, pg_bhh,
                                  eg_Wih, eg_Whh, eg_bih, eg_bhh);

    cls_kernel<<<64, 128>>>(cls_W, cls_b, out);
}

// round 13
// speedup vs baseline: 1.0580x; 1.0580x over previous
#include <cuda_runtime.h>
#include <cuda_bf16.h>

// B=16,U=64,W=32,E=300,H=512,Hh=512,C=7,D=1024,N=1024. KPAD=320+512=832.

__device__ float g_c[2][1024][512];
__device__ float g_feat[1024][1024];
__device__ float g_bias[2][2048];
__device__ __nv_bfloat16 g_Xhi[32][1024][320];
__device__ __nv_bfloat16 g_Xlo[32][1024][320];
__device__ __nv_bfloat16 g_Whi[2][2048][832];
__device__ __nv_bfloat16 g_Wlo[2][2048][832];
__device__ __nv_bfloat16 g_Hhi[2][1024][512];
__device__ __nv_bfloat16 g_Hlo[2][1024][512];
__device__ float g_Agg[64][16][3072];
__device__ float g_Apg[64][16][3072];
__device__ float g_q[64][16][1024];
__device__ float g_hist[65][16][1024];
__device__ float g_p0[16][1024];
__device__ float g_p1[16][1024];
__device__ float g_e[16][512];
__device__ float g_ctx[16][1024];
__device__ float g_es[64][16][512];
__device__ float g_P1a[4][16][3072];
__device__ float g_P1b[4][16][3072];
__device__ float g_P2a[4][16][3072];
__device__ float g_P2b[4][16][3072];
__device__ float g_P3a[4][16][1536];
__device__ float g_P3b[4][16][1536];
__device__ int g_bar_cnt;

__device__ __forceinline__ unsigned long long pk2(float v) {
    unsigned long long r; asm("mov.b64 %0, {%1, %1};" : "=l"(r) : "f"(v)); return r;
}
__device__ __forceinline__ unsigned long long fma2(unsigned long long a, unsigned long long b, unsigned long long c) {
    unsigned long long d; asm("fma.rn.f32x2 %0, %1, %2, %3;" : "=l"(d) : "l"(a), "l"(b), "l"(c)); return d;
}
__device__ __forceinline__ float2 upk2(unsigned long long v) {
    float2 f; asm("mov.b64 {%0, %1}, %2;" : "=f"(f.x), "=f"(f.y) : "l"(v)); return f;
}
__device__ __forceinline__ float sigf(float x) { return 1.0f / (1.0f + __expf(-x)); }
__device__ __forceinline__ float tanhfast(float x) { return 2.0f / (1.0f + __expf(-2.0f * x)) - 1.0f; }
__device__ __forceinline__ unsigned sm_u32(const void* p) { return (unsigned)__cvta_generic_to_shared(p); }
__device__ __forceinline__ void ldsm4(unsigned& r0, unsigned& r1, unsigned& r2, unsigned& r3, unsigned a) {
    asm volatile("ldmatrix.sync.aligned.m8n8.x4.shared.b16 {%0,%1,%2,%3},[%4];"
                 : "=r"(r0), "=r"(r1), "=r"(r2), "=r"(r3) : "r"(a));
}
__device__ __forceinline__ void mma_bf16(float c[4], unsigned a0, unsigned a1, unsigned a2, unsigned a3,
                                         unsigned b0, unsigned b1) {
    asm volatile("mma.sync.aligned.m16n8k16.row.col.f32.bf16.bf16.f32 "
                 "{%0,%1,%2,%3},{%4,%5,%6,%7},{%8,%9},{%0,%1,%2,%3};"
                 : "+f"(c[0]), "+f"(c[1]), "+f"(c[2]), "+f"(c[3])
                 : "r"(a0), "r"(a1), "r"(a2), "r"(a3), "r"(b0), "r"(b1));
}

__global__ void zero_kernel() {
    int i = blockIdx.x * 256 + threadIdx.x;
    if (i == 0) g_bar_cnt = 0;
    if (i < 2 * 1024 * 512) {
        (&g_c[0][0][0])[i] = 0.0f;
        (&g_Hhi[0][0][0])[i] = __float2bfloat16(0.0f);
        (&g_Hlo[0][0][0])[i] = __float2bfloat16(0.0f);
    }
    if (i < 65 * 16 * 1024) (&g_hist[0][0][0])[i] = 0.0f;
    if (i < 16 * 1024) { (&g_p0[0][0])[i] = 0.0f; (&g_p1[0][0])[i] = 0.0f; }
    if (i < 16 * 512) (&g_e[0][0])[i] = 0.0f;
}

__global__ void convert_kernel(const float* __restrict__ x,
                               const float* __restrict__ Wfi, const float* __restrict__ Wfh,
                               const float* __restrict__ Wbi, const float* __restrict__ Wbh,
                               const float* __restrict__ bif, const float* __restrict__ bhf,
                               const float* __restrict__ bib, const float* __restrict__ bhb) {
    int i = blockIdx.x * 256 + threadIdx.x;
    if (i < 32 * 1024 * 320) {
        int e = i % 320, r = i / 320;
        int n = r % 1024, t = r / 1024;
        float v = (e < 300) ? x[n * 9600 + t * 300 + e] : 0.0f;
        __nv_bfloat16 h = __float2bfloat16(v);
        (&g_Xhi[0][0][0])[i] = h;
        (&g_Xlo[0][0][0])[i] = __float2bfloat16(v - __bfloat162float(h));
    }
    if (i < 2 * 2048 * 832) {
        int k = i % 832, r = i / 832;
        int jp = r % 2048, d = r / 2048;
        int row = (jp & 3) * 512 + (jp >> 2);
        const float* Wih = d ? Wbi : Wfi;
        const float* Whh = d ? Wbh : Wfh;
        float v = (k < 300) ? Wih[row * 300 + k] : (k < 320 ? 0.0f : Whh[row * 512 + (k - 320)]);
        __nv_bfloat16 h = __float2bfloat16(v);
        (&g_Whi[0][0][0])[i] = h;
        (&g_Wlo[0][0][0])[i] = __float2bfloat16(v - __bfloat162float(h));
    }
    if (i < 2 * 2048) {
        int d = i >> 11, jp = i & 2047;
        int row = (jp & 3) * 512 + (jp >> 2);
        g_bias[d][jp] = (d ? bib[row] + bhb[row] : bif[row] + bhf[row]);
    }
}

// Fused tensor-core LSTM step. k=32 per iteration (78 iters, 2 tiles/iter),
// syncs halved vs the 156-tile version. Epilogue: bias + cell pointwise.
__global__ __launch_bounds__(256, 2) void lstm_tc(int t, int last) {
    extern __shared__ char smraw[];
    __nv_bfloat16* As = (__nv_bfloat16*)smraw;              // [2][128][40]
    __nv_bfloat16* Bs = (__nv_bfloat16*)(smraw + 20480);    // [2][128][40]
    float* sg = (float*)smraw;                              // [128][132]

    const int dir = blockIdx.z, m0 = blockIdx.y * 128, n0 = blockIdx.x * 128;
    const int tt = dir ? 31 - t : t;
    const int tid = threadIdx.x, lane = tid & 31, wid = tid >> 5;
    const int wm = wid >> 2, wn = wid & 3;
    const int r = tid >> 1, hf = (tid & 1) * 8;

    const __nv_bfloat16* xhi = &g_Xhi[tt][m0 + r][hf];
    const __nv_bfloat16* xlo = &g_Xlo[tt][m0 + r][hf];
    const __nv_bfloat16* hhi = &g_Hhi[dir][m0 + r][hf];
    const __nv_bfloat16* hlo = &g_Hlo[dir][m0 + r][hf];
    const __nv_bfloat16* whi = &g_Whi[dir][n0 + r][hf];
    const __nv_bfloat16* wlo = &g_Wlo[dir][n0 + r][hf];

    float acc[4][4][4];
#pragma unroll
    for (int mi = 0; mi < 4; mi++)
#pragma unroll
        for (int ni = 0; ni < 4; ni++)
#pragma unroll
            for (int q = 0; q < 4; q++) acc[mi][ni][q] = 0.0f;

    uint4 ra0, ra1, rb0, rb1;
    auto fetch = [&](int p) {
        int pass = (p >= 26) + (p >= 52);
        int k = (p - pass * 26) * 32;
        const __nv_bfloat16* ap;
        if (k < 320) ap = (pass == 1 ? xlo : xhi) + k;
        else         ap = (pass == 1 ? hlo : hhi) + (k - 320);
        const __nv_bfloat16* bp = (pass == 2 ? wlo : whi) + k;
        ra0 = *(const uint4*)ap;
        ra1 = *(const uint4*)(ap + 16);
        rb0 = *(const uint4*)bp;
        rb1 = *(const uint4*)(bp + 16);
    };
    auto stage = [&](int buf) {
        *(uint4*)&As[(buf * 128 + r) * 40 + hf]      = ra0;
        *(uint4*)&As[(buf * 128 + r) * 40 + 16 + hf] = ra1;
        *(uint4*)&Bs[(buf * 128 + r) * 40 + hf]      = rb0;
        *(uint4*)&Bs[(buf * 128 + r) * 40 + 16 + hf] = rb1;
    };

    fetch(0);
    stage(0);
    __syncthreads();

    for (int p = 0; p < 78; p++) {
        int cur = p & 1;
        if (p < 77) fetch(p + 1);
#pragma unroll
        for (int half = 0; half < 2; half++) {
            int co = half * 16;
            unsigned a[4][4], bfr[2][4];
#pragma unroll
            for (int mi = 0; mi < 4; mi++) {
                unsigned ad = sm_u32(&As[(cur * 128 + wm * 64 + mi * 16 + (lane & 15)) * 40 + co + (lane >> 4) * 8]);
                ldsm4(a[mi][0], a[mi][1], a[mi][2], a[mi][3], ad);
            }
#pragma unroll
            for (int nb = 0; nb < 2; nb++) {
                unsigned ad = sm_u32(&Bs[(cur * 128 + wn * 32 + nb * 16 + (lane & 15)) * 40 + co + (lane >> 4) * 8]);
                ldsm4(bfr[nb][0], bfr[nb][1], bfr[nb][2], bfr[nb][3], ad);
            }
#pragma unroll
            for (int mi = 0; mi < 4; mi++)
#pragma unroll
                for (int ni = 0; ni < 4; ni++)
                    mma_bf16(acc[mi][ni], a[mi][0], a[mi][1], a[mi][2], a[mi][3],
                             bfr[ni >> 1][ni & 1], bfr[ni >> 1][(ni & 1) + 2]);
        }
        if (p < 77) stage(cur ^ 1);
        __syncthreads();
    }

#pragma unroll
    for (int mi = 0; mi < 4; mi++)
#pragma unroll
        for (int ni = 0; ni < 4; ni++) {
            int mm = wm * 64 + mi * 16 + (lane >> 2);
            int jj = wn * 32 + ni * 8 + (lane & 3) * 2;
            sg[mm * 132 + jj]           = acc[mi][ni][0];
            sg[mm * 132 + jj + 1]       = acc[mi][ni][1];
            sg[(mm + 8) * 132 + jj]     = acc[mi][ni][2];
            sg[(mm + 8) * 132 + jj + 1] = acc[mi][ni][3];
        }
    __syncthreads();

#pragma unroll
    for (int l = 0; l < 16; l++) {
        int idx = tid + 256 * l;
        int m = idx >> 5, kk = idx & 31;
        float4 gq = *(float4*)&sg[m * 132 + 4 * kk];
        float4 bq = *(const float4*)&g_bias[dir][n0 + 4 * kk];
        float gi = gq.x + bq.x, gf = gq.y + bq.y, gg = gq.z + bq.z, go = gq.w + bq.w;
        int kglob = (n0 >> 2) + kk, mg = m0 + m;
        float c = g_c[dir][mg][kglob];
        c = sigf(gf) * c + sigf(gi) * tanhfast(gg);
        float h = sigf(go) * tanhfast(c);
        g_c[dir][mg][kglob] = c;
        __nv_bfloat16 hh = __float2bfloat16(h);
        g_Hhi[dir][mg][kglob] = hh;
        g_Hlo[dir][mg][kglob] = __float2bfloat16(h - __bfloat162float(hh));
        if (last) g_feat[mg][dir * 512 + kglob] = h;
    }
}

__global__ __launch_bounds__(256) void pre_gemm(
    const float* __restrict__ W, const float* __restrict__ bias,
    float* __restrict__ out, int N, int sk, int sj)
{
    __shared__ __align__(16) float As2[16][66];
    __shared__ __align__(16) float Bs2[16][130];
    const int tid = threadIdx.x;
    const int tx = tid & 15, ty = tid >> 4;
    const int m0 = blockIdx.y * 64, j0 = blockIdx.x * 128;
    unsigned long long acc[4][4];
#pragma unroll
    for (int i = 0; i < 4; i++)
#pragma unroll
        for (int c = 0; c < 4; c++) acc[i][c] = 0ULL;
    for (int k0 = 0; k0 < 1024; k0 += 16) {
#pragma unroll
        for (int l = 0; l < 4; l++) {
            int idx = tid + 256 * l;
            int k = idx & 15, rr = m0 + (idx >> 4);
            As2[k][idx >> 4] = g_feat[(rr & 15) * 64 + (rr >> 4)][k0 + k];
        }
#pragma unroll
        for (int l = 0; l < 8; l++) {
            int idx = tid + 256 * l;
            Bs2[idx & 15][idx >> 4] = W[(k0 + (idx & 15)) * sk + (j0 + (idx >> 4)) * sj];
        }
        __syncthreads();
#pragma unroll
        for (int k = 0; k < 16; k++) {
            unsigned long long bv[4];
#pragma unroll
            for (int c = 0; c < 4; c++)
                bv[c] = *reinterpret_cast<const unsigned long long*>(&Bs2[k][2 * tx + 32 * c]);
#pragma unroll
            for (int i = 0; i < 4; i++) {
                unsigned long long av = pk2(As2[k][ty + 16 * i]);
#pragma unroll
                for (int c = 0; c < 4; c++) acc[i][c] = fma2(av, bv[c], acc[i][c]);
            }
        }
        __syncthreads();
    }
#pragma unroll
    for (int i = 0; i < 4; i++) {
        int r = m0 + ty + 16 * i;
#pragma unroll
        for (int c = 0; c < 4; c++) {
            int j = j0 + 2 * tx + 32 * c;
            float2 v = upk2(acc[i][c]);
            out[r * N + j]     = v.x + (bias ? bias[j] : 0.0f);
            out[r * N + j + 1] = v.y + (bias ? bias[j + 1] : 0.0f);
        }
    }
}

// ---------------- persistent phase-2 device functions ----------------------
// Double-buffered M=16 dual-segment GEMM; A tile stride 20 -> float4 LDS.
__device__ void dev_gemm16(int bx, int ks,
    const float* __restrict__ A1, const float* __restrict__ W1, int K1,
    const float* __restrict__ A2, const float* __restrict__ W2, int K2,
    float* __restrict__ part1, float* __restrict__ part2, int N, float* sm)
{
    float (*As2)[16][20] = (float(*)[16][20])sm;           // 2*320 floats
    float (*Bs2)[16][66] = (float(*)[16][66])(sm + 640);   // 2*1056 floats
    const int tid = threadIdx.x;
    const int col = tid & 63, rq = tid >> 6;
    const int j0 = bx * 64;
    const int ka = tid & 15, ra_ = tid >> 4;
    const int it1 = K1 >> 6, itT = it1 + (K2 >> 6);

    float acc1[4] = {0.f, 0.f, 0.f, 0.f};
    float acc2[4] = {0.f, 0.f, 0.f, 0.f};
    float ar, br[4];

    auto fetch = [&](int it) {
        const float* A; const float* W; int K, kb;
        if (it < it1) { A = A1; W = W1; K = K1; kb = ks * (K1 >> 2) + it * 16; }
        else          { A = A2; W = W2; K = K2; kb = ks * (K2 >> 2) + (it - it1) * 16; }
        ar = A[ra_ * K + kb + ka];
#pragma unroll
        for (int l = 0; l < 4; l++) {
            int idx = tid + 256 * l;
            br[l] = W[(j0 + (idx >> 4)) * K + kb + (idx & 15)];
        }
    };

    __syncthreads();
    fetch(0);
    As2[0][ka][ra_] = ar;
#pragma unroll
    for (int l = 0; l < 4; l++) { int idx = tid + 256 * l; Bs2[0][idx & 15][idx >> 4] = br[l]; }
    __syncthreads();

    for (int it = 0; it < itT; it++) {
        int cur = it & 1;
        if (it + 1 < itT) fetch(it + 1);
        float* accp = (it < it1) ? acc1 : acc2;
#pragma unroll
        for (int k = 0; k < 16; k++) {
            float b = Bs2[cur][k][col];
            float4 av = *(float4*)&As2[cur][k][rq * 4];
            accp[0] += av.x * b;
            accp[1] += av.y * b;
            accp[2] += av.z * b;
            accp[3] += av.w * b;
        }
        if (it + 1 < itT) {
            As2[cur ^ 1][ka][ra_] = ar;
#pragma unroll
            for (int l = 0; l < 4; l++) { int idx = tid + 256 * l; Bs2[cur ^ 1][idx & 15][idx >> 4] = br[l]; }
        }
        __syncthreads();
    }

#pragma unroll
    for (int i = 0; i < 4; i++) {
        int rr = rq * 4 + i;
        part1[(ks * 16 + rr) * N + j0 + col] = acc1[i];
        part2[(ks * 16 + rr) * N + j0 + col] = acc2[i];
    }
}

__device__ void dev_combine(int vb,
    const float* __restrict__ pre, const float* __restrict__ bih, const float* __restrict__ bhh,
    const float* __restrict__ part1, const float* __restrict__ part2,
    const float* __restrict__ h, float* __restrict__ outp, float* __restrict__ out2, int Dh)
{
    int idx = vb * 256 + threadIdx.x;
    if (idx >= 16 * Dh) return;
    int b = idx / Dh, j = idx - b * Dh;
    int G = 3 * Dh;
    float gir = 0.f, giz = 0.f, gin = 0.f, ghr = 0.f, ghz = 0.f, ghn = 0.f;
#pragma unroll
    for (int ks = 0; ks < 4; ks++) {
        const float* p1 = part1 + (ks * 16 + b) * G;
        const float* p2 = part2 + (ks * 16 + b) * G;
        gir += p1[j]; giz += p1[Dh + j]; gin += p1[2 * Dh + j];
        ghr += p2[j]; ghz += p2[Dh + j]; ghn += p2[2 * Dh + j];
    }
    if (pre) {
        const float* pp = pre + b * G;
        gir += pp[j]; giz += pp[Dh + j]; gin += pp[2 * Dh + j];
    } else {
        gir += bih[j]; giz += bih[Dh + j]; gin += bih[2 * Dh + j];
    }
    ghr += bhh[j]; ghz += bhh[Dh + j]; ghn += bhh[2 * Dh + j];
    float rg = sigf(gir + ghr);
    float z = sigf(giz + ghz);
    float n = tanhfast(gin + rg * ghn);
    float o = (1.0f - z) * n + z * h[idx];
    outp[idx] = o;
    if (out2) out2[idx] = o;
}

__device__ void dev_attn(int i, int b, float* sm) {
    float* q_s = sm;
    float* sc = sm + 1024;
    const int tid = threadIdx.x;
    __syncthreads();
#pragma unroll
    for (int l = 0; l < 4; l++) q_s[tid + 256 * l] = g_q[i][b][tid + 256 * l];
    __syncthreads();
    const int wid = tid >> 5, lane = tid & 31;
    for (int t = wid; t <= i; t += 8) {
        float s = 0.0f;
        for (int d = lane; d < 1024; d += 32) s += q_s[d] * g_hist[t][b][d];
#pragma unroll
        for (int o = 16; o; o >>= 1) s += __shfl_xor_sync(0xffffffffu, s, o);
        if (lane == 0) sc[t] = s;
    }
    __syncthreads();
    if (tid < 32) {
        float m = -1e30f;
        for (int t = lane; t <= i; t += 32) m = fmaxf(m, sc[t]);
#pragma unroll
        for (int o = 16; o; o >>= 1) m = fmaxf(m, __shfl_xor_sync(0xffffffffu, m, o));
        float s = 0.0f;
        for (int t = lane; t <= i; t += 32) { float e = __expf(sc[t] - m); sc[t] = e; s += e; }
#pragma unroll
        for (int o = 16; o; o >>= 1) s += __shfl_xor_sync(0xffffffffu, s, o);
        float inv = 1.0f / s;
        for (int t = lane; t <= i; t += 32) sc[t] *= inv;
    }
    __syncthreads();
#pragma unroll
    for (int l = 0; l < 4; l++) {
        int d = tid + 256 * l;
        float a = 0.0f;
        for (int t = 0; t <= i; t++) a += sc[t] * g_hist[t][b][d];
        g_ctx[b][d] = a;
    }
    __syncthreads();
}

#define NBLK 152
__device__ __forceinline__ void gbar(int& target) {
    target += NBLK;
    __syncthreads();
    __threadfence();
    if (threadIdx.x == 0) {
        atomicAdd(&g_bar_cnt, 1);
        while (*(volatile int*)&g_bar_cnt < target) __nanosleep(32);
        __threadfence();
    }
    __syncthreads();
}

__global__ __launch_bounds__(256) void phase2_persist(
    const float* __restrict__ gg_Wih, const float* __restrict__ gg_Whh, const float* __restrict__ gg_bhh,
    const float* __restrict__ pg_Wih, const float* __restrict__ pg_Whh, const float* __restrict__ pg_bhh,
    const float* __restrict__ eg_Wih, const float* __restrict__ eg_Whh,
    const float* __restrict__ eg_bih, const float* __restrict__ eg_bhh)
{
    __shared__ __align__(16) float sm[2752];
    int target = 0;
    const int bk = blockIdx.x;
    float* P1a = &g_P1a[0][0][0];
    float* P1b = &g_P1b[0][0][0];
    float* P2a = &g_P2a[0][0][0];
    float* P2b = &g_P2b[0][0][0];
    float* P3a = &g_P3a[0][0][0];
    float* P3b = &g_P3b[0][0][0];

    for (int i = 0; i <= 64; i++) {
        float* p_cur  = (i & 1) ? &g_p1[0][0] : &g_p0[0][0];
        float* p_prev = (i & 1) ? &g_p0[0][0] : &g_p1[0][0];

        for (int vb = bk; vb < 304; vb += NBLK) {
            if (vb < 192) {
                if (i < 64)
                    dev_gemm16(vb % 48, vb / 48, p_cur, gg_Wih, 1024,
                               &g_hist[i][0][0], gg_Whh, 1024, P1a, P1b, 3072, sm);
            } else if (vb < 208) {
                if (i < 64) dev_attn(i, vb - 192, sm);
            } else {
                if (i >= 1)
                    dev_gemm16((vb - 208) % 24, (vb - 208) / 24, p_prev, eg_Wih, 1024,
                               &g_e[0][0], eg_Whh, 512, P3a, P3b, 1536, sm);
            }
        }
        gbar(target);

        for (int vb = bk; vb < 288; vb += NBLK) {
            if (vb < 64) {
                if (i < 64)
                    dev_combine(vb, &g_Agg[i][0][0], nullptr, gg_bhh, P1a, P1b,
                                &g_hist[i][0][0], &g_hist[i + 1][0][0], nullptr, 1024);
            } else if (vb < 96) {
                if (i >= 1)
                    dev_combine(vb - 64, nullptr, eg_bih, eg_bhh, P3a, P3b,
                                &g_e[0][0], &g_e[0][0], &g_es[i - 1][0][0], 512);
            } else {
                if (i < 64)
                    dev_gemm16((vb - 96) % 48, (vb - 96) / 48, &g_ctx[0][0], pg_Wih, 1024,
                               p_cur, pg_Whh, 1024, P2a, P2b, 3072, sm);
            }
        }
        gbar(target);

        if (i < 64) {
            for (int vb = bk; vb < 64; vb += NBLK)
                dev_combine(vb, &g_Apg[i][0][0], nullptr, pg_bhh, P2a, P2b,
                            p_cur, p_cur, nullptr, 1024);
        }
        gbar(target);
    }
}

__global__ void cls_kernel(const float* __restrict__ cls_W, const float* __restrict__ cls_b,
                           float* __restrict__ out) {
    int u = blockIdx.x, tid = threadIdx.x;
    if (tid >= 112) return;
    int b = tid / 7, c = tid - b * 7;
    float s = cls_b[c];
    const float* w = cls_W + c * 512;
    const float* e = &g_es[u][b][0];
    for (int k = 0; k < 512; k++) s += e[k] * w[k];
    out[(b * 64 + u) * 7 + c] = s;
}

extern "C" void kernel_launch(void* const* d_in, const int* in_sizes, int n_in,
                              void* d_out, int out_size) {
    const float* x      = (const float*)d_in[0];
    const float* lWih_f = (const float*)d_in[1];
    const float* lWhh_f = (const float*)d_in[2];
    const float* lbih_f = (const float*)d_in[3];
    const float* lbhh_f = (const float*)d_in[4];
    const float* lWih_b = (const float*)d_in[5];
    const float* lWhh_b = (const float*)d_in[6];
    const float* lbih_b = (const float*)d_in[7];
    const float* lbhh_b = (const float*)d_in[8];
    const float* gg_Wih = (const float*)d_in[9];
    const float* gg_Whh = (const float*)d_in[10];
    const float* gg_bih = (const float*)d_in[11];
    const float* gg_bhh = (const float*)d_in[12];
    const float* Wg     = (const float*)d_in[13];
    const float* pg_Wih = (const float*)d_in[14];
    const float* pg_Whh = (const float*)d_in[15];
    const float* pg_bih = (const float*)d_in[16];
    const float* pg_bhh = (const float*)d_in[17];
    const float* eg_Wih = (const float*)d_in[18];
    const float* eg_Whh = (const float*)d_in[19];
    const float* eg_bih = (const float*)d_in[20];
    const float* eg_bhh = (const float*)d_in[21];
    const float* cls_W  = (const float*)d_in[22];
    const float* cls_b  = (const float*)d_in[23];
    float* out = (float*)d_out;

    float *pAgg, *pApg, *pQ;
    cudaGetSymbolAddress((void**)&pAgg, g_Agg);
    cudaGetSymbolAddress((void**)&pApg, g_Apg);
    cudaGetSymbolAddress((void**)&pQ, g_q);

    static int smem_set = 0;
    if (!smem_set) {
        cudaFuncSetAttribute(lstm_tc, cudaFuncAttributeMaxDynamicSharedMemorySize, 128 * 132 * 4);
        smem_set = 1;
    }

    zero_kernel<<<4160, 256>>>();
    convert_kernel<<<40960, 256>>>(x, lWih_f, lWhh_f, lWih_b, lWhh_b,
                                   lbih_f, lbhh_f, lbih_b, lbhh_b);

    for (int t = 0; t < 32; t++)
        lstm_tc<<<dim3(16, 8, 2), 256, 128 * 132 * 4>>>(t, t == 31);

    pre_gemm<<<dim3(24, 16), 256>>>(gg_Wih, gg_bih, pAgg, 3072, 1, 1024);
    pre_gemm<<<dim3(24, 16), 256>>>(pg_Wih, pg_bih, pApg, 3072, 1, 1024);
    pre_gemm<<<dim3(8, 16), 256>>>(Wg, nullptr, pQ, 1024, 1024, 1);

    phase2_persist<<<NBLK, 256>>>(gg_Wih, gg_Whh, gg_bhh,
                                  pg_Wih, pg_Whh, pg_bhh,
                                  eg_Wih, eg_Whh, eg_bih, eg_bhh);

    cls_kernel<<<64, 128>>>(cls_W, cls_b, out);
}